// round 10
// baseline (speedup 1.0000x reference)
#include <cuda_runtime.h>
#include <cstdint>

// MaxUnpooling2D: B=16, H=128, W=128, C=64, S=2 -> out (16, 256, 256, 64)
// Each (h,w,c) scatters into its OWN 2x2 window at channel c (unique owner
// per output cell) -> one-pass window write, no atomics, no memset.
//
// FINAL (locked, best measured 63.488 us): 1 float4-element/thread,
// 256-thr blocks x 16384, 22 regs, occ ~78%, __ldcg zero-reuse loads,
// default stores.
//
// Roofline verdict: traffic is provably minimal (134 MB reads + 268 MB
// full-line writes = 402.6 MB; gather moves the same, memset+scatter moves
// more). 402.6 MB / 63.5 us = 6.34 TB/s = ~75% of 8 TB/s — the HBM3e
// ceiling for a 1:2 R:W interleaved stream (bus turnaround eats the rest).
// Seven structural levers (cache-op matrix, IPT batching, v8 256-bit ops,
// persistent single-wave grid, block size) all landed within ±0.5%; only
// occupancy-losing variants regressed. No SM pipe >21% busy. Done.

static constexpr int B = 16;
static constexpr int H = 128;
static constexpr int W = 128;
static constexpr int C = 64;
static constexpr int Wo = 256;   // W*2

__global__ __launch_bounds__(256) void unpool_kernel(
    const float4* __restrict__ upd4,
    const int4* __restrict__ msk4,
    float* __restrict__ out)
{
    int tid = blockIdx.x * blockDim.x + threadIdx.x;   // one thread = 4 channels
    // tid layout: [ b*H + h ][ w ][ c4 ], c4 in [0,16)
    int c4 = tid & 15;
    int w  = (tid >> 4) & (W - 1);
    int hb = tid >> 11;            // b*H + h

    float4 u = __ldcg(&upd4[tid]);
    int4   m = __ldcg(&msk4[tid]);

    float4 v0 = {0.f, 0.f, 0.f, 0.f};
    float4 v1 = v0, v2 = v0, v3 = v0;

    // t = mask >> 6 (= y*Wo + x); dx = t & 1; dy = (t >> 8) & 1; q = dy*2+dx
#define PLACE(comp)                                                   \
    {                                                                 \
        int t = m.comp >> 6;                                          \
        int q = ((t >> 7) & 2) | (t & 1);                             \
        v0.comp = (q == 0) ? u.comp : 0.f;                            \
        v1.comp = (q == 1) ? u.comp : 0.f;                            \
        v2.comp = (q == 2) ? u.comp : 0.f;                            \
        v3.comp = (q == 3) ? u.comp : 0.f;                            \
    }
    PLACE(x) PLACE(y) PLACE(z) PLACE(w)
#undef PLACE

    // output base: (2*hb*Wo + 2*w) * C + c4*4
    int base = ((hb * Wo + w) << 1) * C + (c4 << 2);

    *reinterpret_cast<float4*>(out + base)              = v0; // (2h,  2w  )
    *reinterpret_cast<float4*>(out + base + C)          = v1; // (2h,  2w+1)
    *reinterpret_cast<float4*>(out + base + Wo * C)     = v2; // (2h+1,2w  )
    *reinterpret_cast<float4*>(out + base + Wo * C + C) = v3; // (2h+1,2w+1)
}

extern "C" void kernel_launch(void* const* d_in, const int* in_sizes, int n_in,
                              void* d_out, int out_size)
{
    const float4* upd4 = (const float4*)d_in[0];
    const int4*   msk4 = (const int4*)d_in[1];
    float*        out  = (float*)d_out;

    int n4 = (B * H * W * C) / 4;            // 4,194,304 threads
    int threads = 256;
    int blocks = n4 / threads;               // 16384
    unpool_kernel<<<blocks, threads>>>(upd4, msk4, out);
}

// round 11
// speedup vs baseline: 1.0035x; 1.0035x over previous
#include <cuda_runtime.h>
#include <cstdint>

// MaxUnpooling2D: B=16, H=128, W=128, C=64, S=2 -> out (16, 256, 256, 64)
// Each (h,w,c) scatters into its OWN 2x2 window at channel c (unique owner
// per output cell) -> one-pass window write, no atomics, no memset.
//
// FINAL (locked; best measured 63.488 us, noise band 63.49-63.74 over three
// identical runs): 1 float4-element/thread, 256-thr x 16384 blocks, 22 regs,
// occ ~78%, __ldcg zero-reuse loads, default stores.
//
// Roofline verdict: traffic is provably minimal (134 MB reads + 268 MB
// full-line writes = 402.6 MB). 402.6 MB / 63.5 us = 6.34 TB/s = ~75% of
// the 8 TB/s spec — the HBM3e controller ceiling for a 1:2 interleaved
// R:W stream (bus turnaround eats the rest; LTS cap is path-independent,
// so no alternate store path helps). Eight structural levers across ten
// rounds all landed within ±0.5% or regressed via lost occupancy.
// No SM pipe >21% busy. Memory-bound roofline reached.

static constexpr int B = 16;
static constexpr int H = 128;
static constexpr int W = 128;
static constexpr int C = 64;
static constexpr int Wo = 256;   // W*2

__global__ __launch_bounds__(256) void unpool_kernel(
    const float4* __restrict__ upd4,
    const int4* __restrict__ msk4,
    float* __restrict__ out)
{
    int tid = blockIdx.x * blockDim.x + threadIdx.x;   // one thread = 4 channels
    // tid layout: [ b*H + h ][ w ][ c4 ], c4 in [0,16)
    int c4 = tid & 15;
    int w  = (tid >> 4) & (W - 1);
    int hb = tid >> 11;            // b*H + h

    float4 u = __ldcg(&upd4[tid]);
    int4   m = __ldcg(&msk4[tid]);

    float4 v0 = {0.f, 0.f, 0.f, 0.f};
    float4 v1 = v0, v2 = v0, v3 = v0;

    // t = mask >> 6 (= y*Wo + x); dx = t & 1; dy = (t >> 8) & 1; q = dy*2+dx
#define PLACE(comp)                                                   \
    {                                                                 \
        int t = m.comp >> 6;                                          \
        int q = ((t >> 7) & 2) | (t & 1);                             \
        v0.comp = (q == 0) ? u.comp : 0.f;                            \
        v1.comp = (q == 1) ? u.comp : 0.f;                            \
        v2.comp = (q == 2) ? u.comp : 0.f;                            \
        v3.comp = (q == 3) ? u.comp : 0.f;                            \
    }
    PLACE(x) PLACE(y) PLACE(z) PLACE(w)
#undef PLACE

    // output base: (2*hb*Wo + 2*w) * C + c4*4
    int base = ((hb * Wo + w) << 1) * C + (c4 << 2);

    *reinterpret_cast<float4*>(out + base)              = v0; // (2h,  2w  )
    *reinterpret_cast<float4*>(out + base + C)          = v1; // (2h,  2w+1)
    *reinterpret_cast<float4*>(out + base + Wo * C)     = v2; // (2h+1,2w  )
    *reinterpret_cast<float4*>(out + base + Wo * C + C) = v3; // (2h+1,2w+1)
}

extern "C" void kernel_launch(void* const* d_in, const int* in_sizes, int n_in,
                              void* d_out, int out_size)
{
    const float4* upd4 = (const float4*)d_in[0];
    const int4*   msk4 = (const int4*)d_in[1];
    float*        out  = (float*)d_out;

    int n4 = (B * H * W * C) / 4;            // 4,194,304 threads
    int threads = 256;
    int blocks = n4 / threads;               // 16384
    unpool_kernel<<<blocks, threads>>>(upd4, msk4, out);
}